// round 9
// baseline (speedup 1.0000x reference)
#include <cuda_runtime.h>
#include <cuda_fp16.h>

// Problem constants (fixed shapes):
//   x:      (16, 256, 64, 64)  fp32
//   weight: (8, 256)           fp32
//   bias:   (8,)               fp32
//   out:    (16, 256, 128, 128) fp32
#define Bn  16
#define Cn  256
#define Hn  64
#define Wn  64
#define OYn 128
#define OXn 128
#define PLANE (Hn * Wn)        // 4096
#define PADW 65                // padded row stride (uint2 cells)
#define NPX  (OYn * OXn)       // 16384

// fp16-packed input, 4 channels per uint2 cell: [b][cg][h*64+w]. 32 MB.
__device__ uint2 g_xh[Bn * 64 * PLANE];
// Per-pixel corner weights, zero-masked: {half2(w00,w01), half2(w10,w11)}.
__device__ uint2 g_wts[Bn * NPX];
// Per-pixel packed indices: off0(13b) | dx<<13 | off1(13b)<<16.
__device__ unsigned g_idx[Bn * NPX];

__device__ __forceinline__ uint2 packh4(float a, float b, float c, float d)
{
    __half2 lo = __floats2half2_rn(a, b);
    __half2 hi = __floats2half2_rn(c, d);
    uint2 r;
    r.x = *reinterpret_cast<unsigned int*>(&lo);
    r.y = *reinterpret_cast<unsigned int*>(&hi);
    return r;
}

// ---------------------------------------------------------------------------
// Repack kernel: x fp32 -> g_xh fp16x4 cells. Pure streaming.
// ---------------------------------------------------------------------------
__global__ __launch_bounds__(256) void dysample_repack(
    const float* __restrict__ x)
{
    int idx = blockIdx.x * 256 + threadIdx.x;   // 0 .. 1,048,575
    int b   = idx >> 16;
    int r   = idx & 65535;
    int cg  = r >> 10;                          // 0..63
    int pi  = (r & 1023) * 4;                   // pixel base

    const float* p0 = x + ((size_t)b * Cn + (size_t)cg * 4) * PLANE + pi;
    float4 a = *reinterpret_cast<const float4*>(p0);
    float4 c = *reinterpret_cast<const float4*>(p0 + PLANE);
    float4 d = *reinterpret_cast<const float4*>(p0 + 2 * PLANE);
    float4 e = *reinterpret_cast<const float4*>(p0 + 3 * PLANE);

    uint2* dst = g_xh + ((size_t)(b * 64 + cg)) * PLANE + pi;
    uint2 c0 = packh4(a.x, c.x, d.x, e.x);
    uint2 c1 = packh4(a.y, c.y, d.y, e.y);
    uint2 c2 = packh4(a.z, c.z, d.z, e.z);
    uint2 c3 = packh4(a.w, c.w, d.w, e.w);
    *reinterpret_cast<uint4*>(dst)     = make_uint4(c0.x, c0.y, c1.x, c1.y);
    *reinterpret_cast<uint4*>(dst + 2) = make_uint4(c2.x, c2.y, c3.x, c3.y);
}

// ---------------------------------------------------------------------------
// Stage 1: 1x1 conv (8 dots of length 256) + pixel shuffle + weight/index
// descriptor precompute. Block = one (b, h) row: threads = (w, cpart).
// ---------------------------------------------------------------------------
__global__ __launch_bounds__(256) void dysample_stage1(
    const float* __restrict__ x,
    const float* __restrict__ weight,
    const float* __restrict__ bias)
{
    __shared__ float wt[Cn * 8];          // transposed: wt[c*8+o]
    __shared__ float part[4][64][9];      // padded -> conflict-free

    for (int i = threadIdx.x; i < Cn * 8; i += 256)
        wt[(i & 255) * 8 + (i >> 8)] = weight[i];
    __syncthreads();

    int w     = threadIdx.x & 63;
    int cpart = threadIdx.x >> 6;         // 0..3
    int b     = blockIdx.x >> 6;
    int h     = blockIdx.x & 63;

    const float* xb  = x + ((size_t)b * Cn + cpart * 64) * PLANE + h * Wn + w;
    const float* wr0 = &wt[(cpart * 64) * 8];

    float acc[8];
#pragma unroll
    for (int s = 0; s < 8; s++) acc[s] = 0.0f;

#pragma unroll 8
    for (int c = 0; c < 64; ++c) {
        float xv = __ldg(xb + (size_t)c * PLANE);       // coalesced along w
        float4 wa = *reinterpret_cast<const float4*>(wr0 + c * 8);
        float4 wb = *reinterpret_cast<const float4*>(wr0 + c * 8 + 4);
        acc[0] = fmaf(xv, wa.x, acc[0]);
        acc[1] = fmaf(xv, wa.y, acc[1]);
        acc[2] = fmaf(xv, wa.z, acc[2]);
        acc[3] = fmaf(xv, wa.w, acc[3]);
        acc[4] = fmaf(xv, wb.x, acc[4]);
        acc[5] = fmaf(xv, wb.y, acc[5]);
        acc[6] = fmaf(xv, wb.z, acc[6]);
        acc[7] = fmaf(xv, wb.w, acc[7]);
    }

#pragma unroll
    for (int s = 0; s < 8; s++) part[cpart][w][s] = acc[s];
    __syncthreads();

    // Each cpart handles shuffle position s = cpart for its 64 w-pixels.
    {
        int s = cpart;
        float accx = part[0][w][s]     + part[1][w][s]
                   + part[2][w][s]     + part[3][w][s]     + __ldg(&bias[s]);
        float accy = part[0][w][4 + s] + part[1][w][4 + s]
                   + part[2][w][4 + s] + part[3][w][4 + s] + __ldg(&bias[4 + s]);

        // pixel shuffle: out (oy=2h+r1, ox=2w+r2), s=r1*2+r2. Reference
        // quirk: x-coord uses h-linspace at oy; y-coord uses w-linspace at ox.
        int oy = 2 * h + (s >> 1);
        int ox = 2 * w + (s & 1);
        float gx = fmaf((float)oy, 2.0f / 127.0f, -1.0f) + accx;
        float gy = fmaf((float)ox, 2.0f / 127.0f, -1.0f) + accy;
        float ix = fmaf(gx, 32.0f, 31.5f);   // ((g+1)*64 - 1)/2
        float iy = fmaf(gy, 32.0f, 31.5f);

        float fx = floorf(ix), fy = floorf(iy);
        int x0 = (int)fx, y0 = (int)fy;
        float wx = ix - fx, wy = iy - fy;

        int xc0 = min(max(x0, 0), Wn - 1);
        int xc1 = min(max(x0 + 1, 0), Wn - 1);
        int yc0 = min(max(y0, 0), Hn - 1);
        int yc1 = min(max(y0 + 1, 0), Hn - 1);
        unsigned dx = (unsigned)(xc1 - xc0);          // 0 or 1

        // zero-masked axis weights
        float ax0 = ((unsigned)x0       > 63u) ? 0.0f : (1.0f - wx);
        float ax1 = ((unsigned)(x0 + 1) > 63u) ? 0.0f : wx;
        float ay0 = ((unsigned)y0       > 63u) ? 0.0f : (1.0f - wy);
        float ay1 = ((unsigned)(y0 + 1) > 63u) ? 0.0f : wy;

        uint2 wrec = packh4(ay0 * ax0, ay0 * ax1, ay1 * ax0, ay1 * ax1);

        unsigned off0 = (unsigned)(yc0 * PADW + xc0); // <= 4158, 13 bits
        unsigned off1 = (unsigned)(yc1 * PADW + xc0);
        unsigned irec = off0 | (dx << 13) | (off1 << 16);

        size_t pos = (size_t)b * NPX + oy * OXn + ox;
        g_wts[pos] = wrec;
        g_idx[pos] = irec;
    }
}

// ---------------------------------------------------------------------------
// Stage 2: bilinear blend in HFMA2. Block = (b, cg quad, pixel-quarter).
// Corner weights come pre-masked/pre-multiplied as fp16; the whole blend is
// 8 HFMA2-class ops + 4 converts per pixel (4 channels).
// ---------------------------------------------------------------------------
__device__ __forceinline__ float4 sample_one(const uint2* __restrict__ plane,
                                             unsigned wlo, unsigned whi,
                                             unsigned iv)
{
    __half2 wp0 = *reinterpret_cast<const __half2*>(&wlo);  // (w00, w01)
    __half2 wp1 = *reinterpret_cast<const __half2*>(&whi);  // (w10, w11)
    __half2 w00 = __low2half2(wp0),  w01 = __high2half2(wp0);
    __half2 w10 = __low2half2(wp1),  w11 = __high2half2(wp1);

    int e0 = iv & 0x1FFF;
    int dx = (iv >> 13) & 1;
    int e1 = (iv >> 16) & 0x1FFF;

    const uint2* r0 = plane + e0;
    const uint2* r1 = plane + e1;
    uint2 v00 = r0[0], v01 = r0[dx];
    uint2 v10 = r1[0], v11 = r1[dx];

    const __half2* h00 = reinterpret_cast<const __half2*>(&v00);
    const __half2* h01 = reinterpret_cast<const __half2*>(&v01);
    const __half2* h10 = reinterpret_cast<const __half2*>(&v10);
    const __half2* h11 = reinterpret_cast<const __half2*>(&v11);

    __half2 aA = __hmul2(h00[0], w00);
    aA = __hfma2(h01[0], w01, aA);
    aA = __hfma2(h10[0], w10, aA);
    aA = __hfma2(h11[0], w11, aA);

    __half2 aB = __hmul2(h00[1], w00);
    aB = __hfma2(h01[1], w01, aB);
    aB = __hfma2(h10[1], w10, aB);
    aB = __hfma2(h11[1], w11, aB);

    float2 fA = __half22float2(aA);
    float2 fB = __half22float2(aB);
    return make_float4(fA.x, fA.y, fB.x, fB.y);
}

__global__ __launch_bounds__(256, 6) void dysample_stage2(
    float* __restrict__ out)
{
    __shared__ uint2 plane[Hn * PADW];    // 33,280 B -> 6 blocks/SM

    int bid = blockIdx.x;                 // 0..4095
    int q   = bid & 3;                    // pixel quarter
    int cg  = (bid >> 2) & 63;            // channel quad
    int b   = bid >> 8;                   // batch

    // Stage the pre-packed plane: 4096 cells, 2 per thread per iter.
    const uint2* src = g_xh + ((size_t)(b * 64 + cg)) * PLANE;
#pragma unroll
    for (int k = 0; k < 8; ++k) {
        int i = k * 512 + threadIdx.x * 2;
        uint4 v = *reinterpret_cast<const uint4*>(src + i);
        int row = i >> 6, col = i & 63;
        plane[row * PADW + col]     = make_uint2(v.x, v.y);
        plane[row * PADW + col + 1] = make_uint2(v.z, v.w);
    }
    __syncthreads();

    const uint2*    wts = g_wts + (size_t)b * NPX;
    const unsigned* idx = g_idx + (size_t)b * NPX;
    float* o0 = out + ((size_t)(b * Cn + cg * 4)) * NPX;
    float* o1 = o0 + NPX;
    float* o2 = o1 + NPX;
    float* o3 = o2 + NPX;

    // This block's quarter: 4096 pixels, 2 per thread -> 8 iterations.
#pragma unroll 2
    for (int it = 0; it < 8; ++it) {
        int p = q * 4096 + it * 512 + threadIdx.x * 2;
        uint4 wv = *reinterpret_cast<const uint4*>(wts + p);   // 2 px weights
        uint2 iv = *reinterpret_cast<const uint2*>(idx + p);   // 2 px indices

        float4 r0 = sample_one(plane, wv.x, wv.y, iv.x);
        float4 r1 = sample_one(plane, wv.z, wv.w, iv.y);

        *reinterpret_cast<float2*>(o0 + p) = make_float2(r0.x, r1.x);
        *reinterpret_cast<float2*>(o1 + p) = make_float2(r0.y, r1.y);
        *reinterpret_cast<float2*>(o2 + p) = make_float2(r0.z, r1.z);
        *reinterpret_cast<float2*>(o3 + p) = make_float2(r0.w, r1.w);
    }
}

extern "C" void kernel_launch(void* const* d_in, const int* in_sizes, int n_in,
                              void* d_out, int out_size)
{
    const float* x      = (const float*)d_in[0];
    const float* weight = (const float*)d_in[1];
    const float* bias   = (const float*)d_in[2];
    float* out          = (float*)d_out;

    dysample_stage1<<<1024, 256>>>(x, weight, bias);   // 16*64 (b,h) rows
    dysample_repack<<<4096, 256>>>(x);                 // fp32 -> fp16x4
    dysample_stage2<<<4096, 256>>>(out);               // (b, cg, quarter)
}

// round 10
// speedup vs baseline: 1.0736x; 1.0736x over previous
#include <cuda_runtime.h>
#include <cuda_fp16.h>

// Problem constants (fixed shapes):
//   x:      (16, 256, 64, 64)  fp32
//   weight: (8, 256)           fp32
//   bias:   (8,)               fp32
//   out:    (16, 256, 128, 128) fp32
#define Bn  16
#define Cn  256
#define Hn  64
#define Wn  64
#define OYn 128
#define OXn 128
#define PLANE (Hn * Wn)        // 4096
#define PADW 65                // padded row stride (uint2 cells)
#define NPX  (OYn * OXn)       // 16384

// fp16-packed input, 4 channels per uint2 cell: [b][cg][h*64+w]. 32 MB.
__device__ uint2 g_xh[Bn * 64 * PLANE];
// Per-pixel sample descriptor (8 B): {half2(wx,wy),
//   base(14b) | dx<<14 | dy<<15 | zx0<<16 | zx1<<17 | zy0<<18 | zy1<<19}
__device__ uint2 g_samp[Bn * NPX];

__device__ __forceinline__ uint2 packh4(float a, float b, float c, float d)
{
    __half2 lo = __floats2half2_rn(a, b);
    __half2 hi = __floats2half2_rn(c, d);
    uint2 r;
    r.x = *reinterpret_cast<unsigned int*>(&lo);
    r.y = *reinterpret_cast<unsigned int*>(&hi);
    return r;
}

// ---------------------------------------------------------------------------
// Stage 1: 1x1 conv + pixel shuffle + descriptor precompute + fused fp16
// repack of x. Block = one (b, h) row, threads = (w, cpart).
// Loads 8 channels up-front per iteration (MLP 8), THEN packs/stores: keeps
// the R4-proven load batching that the R5 fusion broke.
// ---------------------------------------------------------------------------
__global__ __launch_bounds__(256) void dysample_stage1(
    const float* __restrict__ x,
    const float* __restrict__ weight,
    const float* __restrict__ bias)
{
    __shared__ float wt[Cn * 8];          // transposed: wt[c*8+o]
    __shared__ float part[4][64][9];      // padded -> conflict-free

    for (int i = threadIdx.x; i < Cn * 8; i += 256)
        wt[(i & 255) * 8 + (i >> 8)] = weight[i];
    __syncthreads();

    int w     = threadIdx.x & 63;
    int cpart = threadIdx.x >> 6;         // 0..3
    int b     = blockIdx.x >> 6;
    int h     = blockIdx.x & 63;

    const float* xb  = x + ((size_t)b * Cn + cpart * 64) * PLANE + h * Wn + w;
    const float* wr0 = &wt[(cpart * 64) * 8];
    uint2* xhb = g_xh + ((size_t)(b * 64 + cpart * 16)) * PLANE + h * Wn + w;

    float acc[8];
#pragma unroll
    for (int s = 0; s < 8; s++) acc[s] = 0.0f;

#pragma unroll
    for (int c8 = 0; c8 < 8; ++c8) {
        float v[8];
#pragma unroll
        for (int j = 0; j < 8; ++j)
            v[j] = __ldg(xb + (size_t)(c8 * 8 + j) * PLANE);  // batched, MLP 8
#pragma unroll
        for (int j = 0; j < 8; ++j) {
            const float* wr = wr0 + (c8 * 8 + j) * 8;
            float4 wa = *reinterpret_cast<const float4*>(wr);
            float4 wb = *reinterpret_cast<const float4*>(wr + 4);
            acc[0] = fmaf(v[j], wa.x, acc[0]);
            acc[1] = fmaf(v[j], wa.y, acc[1]);
            acc[2] = fmaf(v[j], wa.z, acc[2]);
            acc[3] = fmaf(v[j], wa.w, acc[3]);
            acc[4] = fmaf(v[j], wb.x, acc[4]);
            acc[5] = fmaf(v[j], wb.y, acc[5]);
            acc[6] = fmaf(v[j], wb.z, acc[6]);
            acc[7] = fmaf(v[j], wb.w, acc[7]);
        }
        // fused fp16 repack: 2 cells per 8 channels (coalesced STG.64)
        xhb[(size_t)(c8 * 2)     * PLANE] = packh4(v[0], v[1], v[2], v[3]);
        xhb[(size_t)(c8 * 2 + 1) * PLANE] = packh4(v[4], v[5], v[6], v[7]);
    }

#pragma unroll
    for (int s = 0; s < 8; s++) part[cpart][w][s] = acc[s];
    __syncthreads();

    // Each cpart handles shuffle position s = cpart for its 64 w-pixels.
    {
        int s = cpart;
        float accx = part[0][w][s]     + part[1][w][s]
                   + part[2][w][s]     + part[3][w][s]     + __ldg(&bias[s]);
        float accy = part[0][w][4 + s] + part[1][w][4 + s]
                   + part[2][w][4 + s] + part[3][w][4 + s] + __ldg(&bias[4 + s]);

        // pixel shuffle: out (oy=2h+r1, ox=2w+r2), s=r1*2+r2. Reference
        // quirk: x-coord uses h-linspace at oy; y-coord uses w-linspace at ox.
        int oy = 2 * h + (s >> 1);
        int ox = 2 * w + (s & 1);
        float gx = fmaf((float)oy, 2.0f / 127.0f, -1.0f) + accx;
        float gy = fmaf((float)ox, 2.0f / 127.0f, -1.0f) + accy;
        float ix = fmaf(gx, 32.0f, 31.5f);   // ((g+1)*64 - 1)/2
        float iy = fmaf(gy, 32.0f, 31.5f);

        float fx = floorf(ix), fy = floorf(iy);
        int x0 = (int)fx, y0 = (int)fy;
        float wx = ix - fx, wy = iy - fy;

        int xc0 = min(max(x0, 0), Wn - 1);
        int xc1 = min(max(x0 + 1, 0), Wn - 1);
        int yc0 = min(max(y0, 0), Hn - 1);
        int yc1 = min(max(y0 + 1, 0), Hn - 1);
        unsigned dx = (unsigned)(xc1 - xc0);          // 0 or 1
        unsigned dy = (unsigned)(yc1 - yc0);
        unsigned zx0 = ((unsigned)x0       > 63u) ? 1u : 0u;
        unsigned zx1 = ((unsigned)(x0 + 1) > 63u) ? 1u : 0u;
        unsigned zy0 = ((unsigned)y0       > 63u) ? 1u : 0u;
        unsigned zy1 = ((unsigned)(y0 + 1) > 63u) ? 1u : 0u;

        unsigned idx = (unsigned)(yc0 * PADW + xc0)
                     | (dx << 14) | (dy << 15)
                     | (zx0 << 16) | (zx1 << 17)
                     | (zy0 << 18) | (zy1 << 19);
        __half2 wxy = __floats2half2_rn(wx, wy);
        uint2 rec;
        rec.x = *reinterpret_cast<unsigned int*>(&wxy);
        rec.y = idx;
        g_samp[(size_t)b * NPX + oy * OXn + ox] = rec;
    }
}

// ---------------------------------------------------------------------------
// Stage 2: bilinear blend only. Block = (b, cg quad, pixel-quarter).
// R5-measured 74.6us mainloop + one-ahead descriptor prefetch to hide the
// L2-latency LDG that caps issue at 42%.
// ---------------------------------------------------------------------------
__device__ __forceinline__ void unpack4(uint2 v, float2& p01, float2& p23)
{
    p01 = __half22float2(*reinterpret_cast<const __half2*>(&v.x));
    p23 = __half22float2(*reinterpret_cast<const __half2*>(&v.y));
}

__device__ __forceinline__ float4 sample_one(const uint2* __restrict__ plane,
                                             unsigned wbits, unsigned idx)
{
    float2 wxy = __half22float2(*reinterpret_cast<const __half2*>(&wbits));
    float wx = wxy.x, wy = wxy.y;

    int base = idx & 0x3FFF;
    int dx   = (idx >> 14) & 1;
    int dy   = (idx >> 15) & 1;
    float ax0 = (idx & (1u << 16)) ? 0.0f : (1.0f - wx);
    float ax1 = (idx & (1u << 17)) ? 0.0f : wx;
    float ay0 = (idx & (1u << 18)) ? 0.0f : (1.0f - wy);
    float ay1 = (idx & (1u << 19)) ? 0.0f : wy;

    float w00 = ay0 * ax0, w01 = ay0 * ax1;
    float w10 = ay1 * ax0, w11 = ay1 * ax1;

    const uint2* r0p = plane + base;
    const uint2* r1p = r0p + (dy ? PADW : 0);
    uint2 v00 = r0p[0], v01 = r0p[dx];
    uint2 v10 = r1p[0], v11 = r1p[dx];

    float2 a01, a23, b01, b23;
    unpack4(v00, a01, a23);
    unpack4(v01, b01, b23);
    float rx = a01.x * w00 + b01.x * w01;
    float ry = a01.y * w00 + b01.y * w01;
    float rz = a23.x * w00 + b23.x * w01;
    float rw = a23.y * w00 + b23.y * w01;
    unpack4(v10, a01, a23);
    unpack4(v11, b01, b23);
    rx = fmaf(a01.x, w10, fmaf(b01.x, w11, rx));
    ry = fmaf(a01.y, w10, fmaf(b01.y, w11, ry));
    rz = fmaf(a23.x, w10, fmaf(b23.x, w11, rz));
    rw = fmaf(a23.y, w10, fmaf(b23.y, w11, rw));
    return make_float4(rx, ry, rz, rw);
}

__global__ __launch_bounds__(256, 6) void dysample_stage2(
    float* __restrict__ out)
{
    __shared__ uint2 plane[Hn * PADW];    // 33,280 B -> 6 blocks/SM

    int bid = blockIdx.x;                 // 0..4095
    int q   = bid & 3;                    // pixel quarter
    int cg  = (bid >> 2) & 63;            // channel quad
    int b   = bid >> 8;                   // batch

    // Stage the pre-packed plane: 4096 cells, 2 per thread per iter.
    const uint2* src = g_xh + ((size_t)(b * 64 + cg)) * PLANE;
#pragma unroll
    for (int k = 0; k < 8; ++k) {
        int i = k * 512 + threadIdx.x * 2;
        uint4 v = *reinterpret_cast<const uint4*>(src + i);
        int row = i >> 6, col = i & 63;
        plane[row * PADW + col]     = make_uint2(v.x, v.y);
        plane[row * PADW + col + 1] = make_uint2(v.z, v.w);
    }
    __syncthreads();

    const uint2* samp = g_samp + (size_t)b * NPX + q * 4096;
    float* o0 = out + ((size_t)(b * Cn + cg * 4)) * NPX + q * 4096;
    float* o1 = o0 + NPX;
    float* o2 = o1 + NPX;
    float* o3 = o2 + NPX;

    int p0 = threadIdx.x * 2;
    // One-iteration-ahead descriptor prefetch pipeline.
    uint4 sv = *reinterpret_cast<const uint4*>(samp + p0);

#pragma unroll
    for (int it = 0; it < 8; ++it) {
        int p = it * 512 + p0;
        uint4 cur = sv;
        if (it < 7)
            sv = *reinterpret_cast<const uint4*>(samp + p + 512);

        float4 r0 = sample_one(plane, cur.x, cur.y);
        float4 r1 = sample_one(plane, cur.z, cur.w);

        *reinterpret_cast<float2*>(o0 + p) = make_float2(r0.x, r1.x);
        *reinterpret_cast<float2*>(o1 + p) = make_float2(r0.y, r1.y);
        *reinterpret_cast<float2*>(o2 + p) = make_float2(r0.z, r1.z);
        *reinterpret_cast<float2*>(o3 + p) = make_float2(r0.w, r1.w);
    }
}

extern "C" void kernel_launch(void* const* d_in, const int* in_sizes, int n_in,
                              void* d_out, int out_size)
{
    const float* x      = (const float*)d_in[0];
    const float* weight = (const float*)d_in[1];
    const float* bias   = (const float*)d_in[2];
    float* out          = (float*)d_out;

    dysample_stage1<<<1024, 256>>>(x, weight, bias);   // 16*64 (b,h) rows
    dysample_stage2<<<4096, 256>>>(out);               // (b, cg, quarter)
}

// round 11
// speedup vs baseline: 1.0871x; 1.0125x over previous
#include <cuda_runtime.h>
#include <cuda_fp16.h>

// Problem constants (fixed shapes):
//   x:      (16, 256, 64, 64)  fp32
//   weight: (8, 256)           fp32
//   bias:   (8,)               fp32
//   out:    (16, 256, 128, 128) fp32
#define Bn  16
#define Cn  256
#define Hn  64
#define Wn  64
#define OYn 128
#define OXn 128
#define PLANE (Hn * Wn)        // 4096
#define PADW 65                // padded row stride (uint2 cells)
#define NPX  (OYn * OXn)       // 16384

// fp16-packed input, 4 channels per uint2 cell: [b][cg][h*64+w]. 32 MB.
__device__ uint2 g_xh[Bn * 64 * PLANE];
// Per-pixel sample descriptor (8 B): {half2(wx,wy),
//   base(14b) | dx<<14 | dy<<15 | zx0<<16 | zx1<<17 | zy0<<18 | zy1<<19}
__device__ uint2 g_samp[Bn * NPX];

__device__ __forceinline__ uint2 packh4(float a, float b, float c, float d)
{
    __half2 lo = __floats2half2_rn(a, b);
    __half2 hi = __floats2half2_rn(c, d);
    uint2 r;
    r.x = *reinterpret_cast<unsigned int*>(&lo);
    r.y = *reinterpret_cast<unsigned int*>(&hi);
    return r;
}

// ---------------------------------------------------------------------------
// Repack kernel: x fp32 -> g_xh fp16x4 cells. Pure streaming; runs on a side
// stream CONCURRENTLY with stage1 (no dependency between them).
// ---------------------------------------------------------------------------
__global__ __launch_bounds__(256) void dysample_repack(
    const float* __restrict__ x)
{
    int idx = blockIdx.x * 256 + threadIdx.x;   // 0 .. 1,048,575
    int b   = idx >> 16;
    int r   = idx & 65535;
    int cg  = r >> 10;                          // 0..63
    int pi  = (r & 1023) * 4;                   // pixel base

    const float* p0 = x + ((size_t)b * Cn + (size_t)cg * 4) * PLANE + pi;
    float4 a = *reinterpret_cast<const float4*>(p0);
    float4 c = *reinterpret_cast<const float4*>(p0 + PLANE);
    float4 d = *reinterpret_cast<const float4*>(p0 + 2 * PLANE);
    float4 e = *reinterpret_cast<const float4*>(p0 + 3 * PLANE);

    uint2* dst = g_xh + ((size_t)(b * 64 + cg)) * PLANE + pi;
    uint2 c0 = packh4(a.x, c.x, d.x, e.x);
    uint2 c1 = packh4(a.y, c.y, d.y, e.y);
    uint2 c2 = packh4(a.z, c.z, d.z, e.z);
    uint2 c3 = packh4(a.w, c.w, d.w, e.w);
    *reinterpret_cast<uint4*>(dst)     = make_uint4(c0.x, c0.y, c1.x, c1.y);
    *reinterpret_cast<uint4*>(dst + 2) = make_uint4(c2.x, c2.y, c3.x, c3.y);
}

// ---------------------------------------------------------------------------
// Stage 1 (lean, no repack): 1x1 conv + pixel shuffle + descriptor emit.
// Block = one (b, h) row: threads = (w, cpart). Measured 19.5us (R8).
// ---------------------------------------------------------------------------
__global__ __launch_bounds__(256) void dysample_stage1(
    const float* __restrict__ x,
    const float* __restrict__ weight,
    const float* __restrict__ bias)
{
    __shared__ float wt[Cn * 8];          // transposed: wt[c*8+o]
    __shared__ float part[4][64][9];      // padded -> conflict-free

    for (int i = threadIdx.x; i < Cn * 8; i += 256)
        wt[(i & 255) * 8 + (i >> 8)] = weight[i];
    __syncthreads();

    int w     = threadIdx.x & 63;
    int cpart = threadIdx.x >> 6;         // 0..3
    int b     = blockIdx.x >> 6;
    int h     = blockIdx.x & 63;

    const float* xb  = x + ((size_t)b * Cn + cpart * 64) * PLANE + h * Wn + w;
    const float* wr0 = &wt[(cpart * 64) * 8];

    float acc[8];
#pragma unroll
    for (int s = 0; s < 8; s++) acc[s] = 0.0f;

#pragma unroll 8
    for (int c = 0; c < 64; ++c) {
        float xv = __ldg(xb + (size_t)c * PLANE);       // coalesced along w
        float4 wa = *reinterpret_cast<const float4*>(wr0 + c * 8);
        float4 wb = *reinterpret_cast<const float4*>(wr0 + c * 8 + 4);
        acc[0] = fmaf(xv, wa.x, acc[0]);
        acc[1] = fmaf(xv, wa.y, acc[1]);
        acc[2] = fmaf(xv, wa.z, acc[2]);
        acc[3] = fmaf(xv, wa.w, acc[3]);
        acc[4] = fmaf(xv, wb.x, acc[4]);
        acc[5] = fmaf(xv, wb.y, acc[5]);
        acc[6] = fmaf(xv, wb.z, acc[6]);
        acc[7] = fmaf(xv, wb.w, acc[7]);
    }

#pragma unroll
    for (int s = 0; s < 8; s++) part[cpart][w][s] = acc[s];
    __syncthreads();

    // Each cpart handles shuffle position s = cpart for its 64 w-pixels.
    {
        int s = cpart;
        float accx = part[0][w][s]     + part[1][w][s]
                   + part[2][w][s]     + part[3][w][s]     + __ldg(&bias[s]);
        float accy = part[0][w][4 + s] + part[1][w][4 + s]
                   + part[2][w][4 + s] + part[3][w][4 + s] + __ldg(&bias[4 + s]);

        // pixel shuffle: out (oy=2h+r1, ox=2w+r2), s=r1*2+r2. Reference
        // quirk: x-coord uses h-linspace at oy; y-coord uses w-linspace at ox.
        int oy = 2 * h + (s >> 1);
        int ox = 2 * w + (s & 1);
        float gx = fmaf((float)oy, 2.0f / 127.0f, -1.0f) + accx;
        float gy = fmaf((float)ox, 2.0f / 127.0f, -1.0f) + accy;
        float ix = fmaf(gx, 32.0f, 31.5f);   // ((g+1)*64 - 1)/2
        float iy = fmaf(gy, 32.0f, 31.5f);

        float fx = floorf(ix), fy = floorf(iy);
        int x0 = (int)fx, y0 = (int)fy;
        float wx = ix - fx, wy = iy - fy;

        int xc0 = min(max(x0, 0), Wn - 1);
        int xc1 = min(max(x0 + 1, 0), Wn - 1);
        int yc0 = min(max(y0, 0), Hn - 1);
        int yc1 = min(max(y0 + 1, 0), Hn - 1);
        unsigned dx = (unsigned)(xc1 - xc0);          // 0 or 1
        unsigned dy = (unsigned)(yc1 - yc0);
        unsigned zx0 = ((unsigned)x0       > 63u) ? 1u : 0u;
        unsigned zx1 = ((unsigned)(x0 + 1) > 63u) ? 1u : 0u;
        unsigned zy0 = ((unsigned)y0       > 63u) ? 1u : 0u;
        unsigned zy1 = ((unsigned)(y0 + 1) > 63u) ? 1u : 0u;

        unsigned idx = (unsigned)(yc0 * PADW + xc0)
                     | (dx << 14) | (dy << 15)
                     | (zx0 << 16) | (zx1 << 17)
                     | (zy0 << 18) | (zy1 << 19);
        __half2 wxy = __floats2half2_rn(wx, wy);
        uint2 rec;
        rec.x = *reinterpret_cast<unsigned int*>(&wxy);
        rec.y = idx;
        g_samp[(size_t)b * NPX + oy * OXn + ox] = rec;
    }
}

// ---------------------------------------------------------------------------
// Stage 2: bilinear blend only (measured 74.6us mainloop, unchanged except
// streaming output stores). Block = (b, cg quad, pixel-quarter).
// ---------------------------------------------------------------------------
__device__ __forceinline__ void unpack4(uint2 v, float2& p01, float2& p23)
{
    p01 = __half22float2(*reinterpret_cast<const __half2*>(&v.x));
    p23 = __half22float2(*reinterpret_cast<const __half2*>(&v.y));
}

__device__ __forceinline__ float4 sample_one(const uint2* __restrict__ plane,
                                             unsigned wbits, unsigned idx)
{
    float2 wxy = __half22float2(*reinterpret_cast<const __half2*>(&wbits));
    float wx = wxy.x, wy = wxy.y;

    int base = idx & 0x3FFF;
    int dx   = (idx >> 14) & 1;
    int dy   = (idx >> 15) & 1;
    float ax0 = (idx & (1u << 16)) ? 0.0f : (1.0f - wx);
    float ax1 = (idx & (1u << 17)) ? 0.0f : wx;
    float ay0 = (idx & (1u << 18)) ? 0.0f : (1.0f - wy);
    float ay1 = (idx & (1u << 19)) ? 0.0f : wy;

    float w00 = ay0 * ax0, w01 = ay0 * ax1;
    float w10 = ay1 * ax0, w11 = ay1 * ax1;

    const uint2* r0p = plane + base;
    const uint2* r1p = r0p + (dy ? PADW : 0);
    uint2 v00 = r0p[0], v01 = r0p[dx];
    uint2 v10 = r1p[0], v11 = r1p[dx];

    float2 a01, a23, b01, b23;
    unpack4(v00, a01, a23);
    unpack4(v01, b01, b23);
    float rx = a01.x * w00 + b01.x * w01;
    float ry = a01.y * w00 + b01.y * w01;
    float rz = a23.x * w00 + b23.x * w01;
    float rw = a23.y * w00 + b23.y * w01;
    unpack4(v10, a01, a23);
    unpack4(v11, b01, b23);
    rx = fmaf(a01.x, w10, fmaf(b01.x, w11, rx));
    ry = fmaf(a01.y, w10, fmaf(b01.y, w11, ry));
    rz = fmaf(a23.x, w10, fmaf(b23.x, w11, rz));
    rw = fmaf(a23.y, w10, fmaf(b23.y, w11, rw));
    return make_float4(rx, ry, rz, rw);
}

__global__ __launch_bounds__(256, 6) void dysample_stage2(
    float* __restrict__ out)
{
    __shared__ uint2 plane[Hn * PADW];    // 33,280 B -> 6 blocks/SM

    int bid = blockIdx.x;                 // 0..4095
    int q   = bid & 3;                    // pixel quarter
    int cg  = (bid >> 2) & 63;            // channel quad
    int b   = bid >> 8;                   // batch

    // Stage the pre-packed plane: 4096 cells, 2 per thread per iter.
    const uint2* src = g_xh + ((size_t)(b * 64 + cg)) * PLANE;
#pragma unroll
    for (int k = 0; k < 8; ++k) {
        int i = k * 512 + threadIdx.x * 2;
        uint4 v = *reinterpret_cast<const uint4*>(src + i);
        int row = i >> 6, col = i & 63;
        plane[row * PADW + col]     = make_uint2(v.x, v.y);
        plane[row * PADW + col + 1] = make_uint2(v.z, v.w);
    }
    __syncthreads();

    const uint2* samp = g_samp + (size_t)b * NPX + q * 4096;
    float* o0 = out + ((size_t)(b * Cn + cg * 4)) * NPX + q * 4096;
    float* o1 = o0 + NPX;
    float* o2 = o1 + NPX;
    float* o3 = o2 + NPX;

    int p0 = threadIdx.x * 2;
    uint4 sv = *reinterpret_cast<const uint4*>(samp + p0);

#pragma unroll
    for (int it = 0; it < 8; ++it) {
        int p = it * 512 + p0;
        uint4 cur = sv;
        if (it < 7)
            sv = *reinterpret_cast<const uint4*>(samp + p + 512);

        float4 r0 = sample_one(plane, cur.x, cur.y);
        float4 r1 = sample_one(plane, cur.z, cur.w);

        // Streaming stores: output is never re-read; keep it out of L2's way.
        __stcs(reinterpret_cast<float2*>(o0 + p), make_float2(r0.x, r1.x));
        __stcs(reinterpret_cast<float2*>(o1 + p), make_float2(r0.y, r1.y));
        __stcs(reinterpret_cast<float2*>(o2 + p), make_float2(r0.z, r1.z));
        __stcs(reinterpret_cast<float2*>(o3 + p), make_float2(r0.w, r1.w));
    }
}

extern "C" void kernel_launch(void* const* d_in, const int* in_sizes, int n_in,
                              void* d_out, int out_size)
{
    const float* x      = (const float*)d_in[0];
    const float* weight = (const float*)d_in[1];
    const float* bias   = (const float*)d_in[2];
    float* out          = (float*)d_out;

    // One-time creation of side stream + fork/join events (handles only; no
    // device memory). Same launch topology every call.
    static cudaStream_t s_side = nullptr;
    static cudaEvent_t  ev_fork = nullptr, ev_join = nullptr;
    if (s_side == nullptr) {
        cudaStreamCreateWithFlags(&s_side, cudaStreamNonBlocking);
        cudaEventCreateWithFlags(&ev_fork, cudaEventDisableTiming);
        cudaEventCreateWithFlags(&ev_join, cudaEventDisableTiming);
    }

    // Fork: repack (side stream) runs concurrently with stage1 (main stream).
    cudaEventRecord(ev_fork, 0);
    cudaStreamWaitEvent(s_side, ev_fork, 0);

    dysample_stage1<<<1024, 256>>>(x, weight, bias);   // main: conv+descr
    dysample_repack<<<4096, 256, 0, s_side>>>(x);      // side: fp32->fp16x4

    // Join: stage2 needs both g_samp (main) and g_xh (side).
    cudaEventRecord(ev_join, s_side);
    cudaStreamWaitEvent(0, ev_join, 0);

    dysample_stage2<<<4096, 256>>>(out);               // (b, cg, quarter)
}